// round 15
// baseline (speedup 1.0000x reference)
#include <cuda_runtime.h>
#include <cuda_fp16.h>
#include <cstdint>

#define B_TOK 8192
#define DDIM  1024
#define HDIM  2048
#define ODIM  1024
#define NEXP  8

#define MT 128
#define NT 128
#define KC 64
#define NTHR 256

// ---------------- scratch (device globals: allocation-free rule) -------------
__device__ int   g_count[NEXP];
__device__ int   g_list[NEXP * B_TOK];     // entry = token*2 + slot
__device__ float g_wlist[NEXP * B_TOK];
__device__ alignas(128) __half g_x16[(size_t)B_TOK * DDIM];
__device__ alignas(128) __half g_W1t[(size_t)NEXP * HDIM * DDIM];  // [E][H][D] fp16
__device__ alignas(128) __half g_W2t[(size_t)NEXP * ODIM * HDIM];  // [E][O][H] fp16
__device__ alignas(128) __half g_h16[(size_t)2 * B_TOK * HDIM];    // [16384][H]

// ---------------- helpers ----------------------------------------------------
__device__ __forceinline__ uint32_t smem_u32(const void* p) {
    uint32_t a;
    asm("{ .reg .u64 t; cvta.to.shared.u64 t, %1; cvt.u32.u64 %0, t; }"
        : "=r"(a) : "l"(p));
    return a;
}
#define SW(o) ((o) ^ (((o) >> 3) & 0x70))

__device__ __forceinline__ void ldsm4(uint32_t* r, uint32_t a) {
    asm volatile("ldmatrix.sync.aligned.m8n8.x4.shared.b16 {%0,%1,%2,%3}, [%4];"
        : "=r"(r[0]), "=r"(r[1]), "=r"(r[2]), "=r"(r[3]) : "r"(a));
}
__device__ __forceinline__ void mma16816(float* c, const uint32_t* a, const uint32_t* b) {
    asm volatile("mma.sync.aligned.m16n8k16.row.col.f32.f16.f16.f32 "
        "{%0,%1,%2,%3}, {%4,%5,%6,%7}, {%8,%9}, {%0,%1,%2,%3};"
        : "+f"(c[0]), "+f"(c[1]), "+f"(c[2]), "+f"(c[3])
        : "r"(a[0]), "r"(a[1]), "r"(a[2]), "r"(a[3]), "r"(b[0]), "r"(b[1]));
}
#define CP16(dst, src) \
    asm volatile("cp.async.cg.shared.global [%0], [%1], 16;" :: "r"(dst), "l"(src))
#define CP_COMMIT() asm volatile("cp.async.commit_group;" ::: "memory")
#define CP_WAIT1()  asm volatile("cp.async.wait_group 1;" ::: "memory")
#define CP_WAIT0()  asm volatile("cp.async.wait_group 0;" ::: "memory")

__device__ __forceinline__ uint32_t pkh(__half a, __half b) {
    return (uint32_t)__half_as_ushort(a) | ((uint32_t)__half_as_ushort(b) << 16);
}

// ---------------- SMEM layout ------------------------------------------------
// [0,512) sEnt  [512,1024) sW  [1024,1536) sBias (128 floats)
// [2048, +3*32K): 3 pipeline stages, each [A 16K | B 16K]
#define OFF_ENT  0
#define OFF_W    512
#define OFF_BIAS 1024
#define OFF_T    2048
#define B_OFF    16384
#define STAGE    32768
#define SMEM_BYTES (OFF_T + 3 * STAGE)   // 100352 -> 2 CTAs/SM

// ============================ gating (+x cast, +out zeroing fused) ===========
__global__ void zero_counts_kernel() {
    if (threadIdx.x < NEXP) g_count[threadIdx.x] = 0;
}

__global__ void gate_kernel(const float* __restrict__ x,
                            const float* __restrict__ Wg,
                            const float* __restrict__ bg,
                            float* __restrict__ out) {
    int gw   = (blockIdx.x * blockDim.x + threadIdx.x) >> 5;
    int lane = threadIdx.x & 31;
    if (gw >= B_TOK) return;
    {
        float4* orow = reinterpret_cast<float4*>(out + (size_t)gw * ODIM);
        float4 z = make_float4(0.f, 0.f, 0.f, 0.f);
#pragma unroll
        for (int i = 0; i < ODIM / 4 / 32; i++)
            orow[lane + 32 * i] = z;
    }
    const float* xr = x + (size_t)gw * DDIM;
    __half* xo = g_x16 + (size_t)gw * DDIM;
    float acc[NEXP];
#pragma unroll
    for (int e = 0; e < NEXP; e++) acc[e] = 0.f;
    for (int d = lane; d < DDIM; d += 32) {
        float xv = xr[d];
        xo[d] = __float2half_rn(xv);
        const float4* w4 = reinterpret_cast<const float4*>(Wg + (size_t)d * NEXP);
        float4 w0 = w4[0], w1 = w4[1];
        acc[0] += xv * w0.x; acc[1] += xv * w0.y;
        acc[2] += xv * w0.z; acc[3] += xv * w0.w;
        acc[4] += xv * w1.x; acc[5] += xv * w1.y;
        acc[6] += xv * w1.z; acc[7] += xv * w1.w;
    }
#pragma unroll
    for (int off = 16; off; off >>= 1)
#pragma unroll
        for (int e = 0; e < NEXP; e++)
            acc[e] += __shfl_xor_sync(0xFFFFFFFFu, acc[e], off);
    if (lane == 0) {
        float s[NEXP];
#pragma unroll
        for (int e = 0; e < NEXP; e++) s[e] = acc[e] + bg[e];
        float M = s[0];
#pragma unroll
        for (int e = 1; e < NEXP; e++) M = fmaxf(M, s[e]);
        float p[NEXP], Z = 0.f;
#pragma unroll
        for (int e = 0; e < NEXP; e++) { p[e] = expf(s[e] - M); Z += p[e]; }
        int i1 = 0;
#pragma unroll
        for (int e = 1; e < NEXP; e++) if (s[e] > s[i1]) i1 = e;
        int i2 = -1;
#pragma unroll
        for (int e = 0; e < NEXP; e++)
            if (e != i1 && (i2 < 0 || s[e] > s[i2])) i2 = e;
        float denom = p[i1] + p[i2] + 1e-8f * Z;
        float w1 = p[i1] / denom;
        float w2 = p[i2] / denom;
        int pos1 = atomicAdd(&g_count[i1], 1);
        g_list[i1 * B_TOK + pos1]  = gw * 2 + 0;
        g_wlist[i1 * B_TOK + pos1] = w1;
        int pos2 = atomicAdd(&g_count[i2], 1);
        g_list[i2 * B_TOK + pos2]  = gw * 2 + 1;
        g_wlist[i2 * B_TOK + pos2] = w2;
    }
}

// ============ weight transpose + fp16 cast ===================================
__global__ void convW1_kernel(const float* __restrict__ W1) {
    __shared__ float ts[32][33];
    int e = blockIdx.z;
    int h0 = blockIdx.x * 32, d0 = blockIdx.y * 32;
    int tx = threadIdx.x, ty = threadIdx.y;
    const float* src = W1 + ((size_t)e * DDIM + d0) * HDIM + h0;
#pragma unroll
    for (int j = 0; j < 4; j++)
        ts[ty + 8 * j][tx] = src[(size_t)(ty + 8 * j) * HDIM + tx];
    __syncthreads();
    int t = ty * 32 + tx;
    int r = t >> 3;
    int c = t & 7;
    __half v0 = __float2half_rn(ts[4 * c + 0][r]);
    __half v1 = __float2half_rn(ts[4 * c + 1][r]);
    __half v2 = __float2half_rn(ts[4 * c + 2][r]);
    __half v3 = __float2half_rn(ts[4 * c + 3][r]);
    *reinterpret_cast<uint2*>(g_W1t + ((size_t)e * HDIM + h0 + r) * DDIM + d0 + 4 * c) =
        make_uint2(pkh(v0, v1), pkh(v2, v3));
}

__global__ void convW2_kernel(const float* __restrict__ W2) {
    __shared__ float ts[32][33];
    int e = blockIdx.z;
    int o0 = blockIdx.x * 32, h0 = blockIdx.y * 32;
    int tx = threadIdx.x, ty = threadIdx.y;
    const float* src = W2 + ((size_t)e * HDIM + h0) * ODIM + o0;
#pragma unroll
    for (int j = 0; j < 4; j++)
        ts[ty + 8 * j][tx] = src[(size_t)(ty + 8 * j) * ODIM + tx];
    __syncthreads();
    int t = ty * 32 + tx;
    int r = t >> 3;
    int c = t & 7;
    __half v0 = __float2half_rn(ts[4 * c + 0][r]);
    __half v1 = __float2half_rn(ts[4 * c + 1][r]);
    __half v2 = __float2half_rn(ts[4 * c + 2][r]);
    __half v3 = __float2half_rn(ts[4 * c + 3][r]);
    *reinterpret_cast<uint2*>(g_W2t + ((size_t)e * ODIM + o0 + r) * HDIM + h0 + 4 * c) =
        make_uint2(pkh(v0, v1), pkh(v2, v3));
}

// ============================ GEMM core ======================================
// 8 warps (2 M x 4 N); warp tile 64x32; single-buffered fragments.
__device__ __forceinline__ void mma_stage(uint32_t sb, int st,
                                          int rA, int aSel, int rB, int bSel,
                                          float acc[4][4][4]) {
    const uint32_t AB = sb + OFF_T + (uint32_t)st * STAGE;
    const uint32_t BB = AB + B_OFF;
#pragma unroll
    for (int k16 = 0; k16 < 4; k16++) {
        const uint32_t kb = (uint32_t)k16 * 32;
        uint32_t bf[2][4], af[4][4];
#pragma unroll
        for (int g = 0; g < 2; g++)
            ldsm4(bf[g], BB + SW((uint32_t)(rB + g * 16) * 128 + kb + bSel * 16));
#pragma unroll
        for (int mi = 0; mi < 4; mi++)
            ldsm4(af[mi], AB + SW((uint32_t)(rA + mi * 16) * 128 + kb + aSel * 16));
#pragma unroll
        for (int mi = 0; mi < 4; mi++)
#pragma unroll
            for (int ni = 0; ni < 4; ni++)
                mma16816(acc[mi][ni], af[mi], &bf[ni >> 1][(ni & 1) * 2]);
    }
}

// ---------------- GEMM1: h = relu(x_g @ W1t^T + b1) --------------------------
__global__ __launch_bounds__(NTHR, 2)
void gemm1_mma(const float* __restrict__ b1) {
    const int e = blockIdx.z;
    const int count = g_count[e];
    const int r0 = blockIdx.y * MT;
    if (r0 >= count) return;
    const int n0 = blockIdx.x * NT;

    extern __shared__ char smem[];
    const uint32_t sb = smem_u32(smem);
    const int t = threadIdx.x, wid = t >> 5, lane = t & 31;

    int*   sEnt  = (int*)(smem + OFF_ENT);
    float* sBias = (float*)(smem + OFF_BIAS);
    if (t < 128) {
        int pos = r0 + t;
        sEnt[t]  = (pos < count) ? g_list[e * B_TOK + pos] : -1;
        sBias[t] = b1[(size_t)e * HDIM + n0 + t];
    }
    __syncthreads();

    // A copy: row r = t>>1 (0..127), 64B half (t&1), 4 chunks
    const int r = t >> 1;
    const int half = t & 1;
    const int ent = sEnt[r];
    const int tok = (ent < 0 ? 0 : ent) >> 1;
    const __half* aS = g_x16 + (size_t)tok * DDIM + half * 32;
    // B copy: row r (0..127), 64B half, 4 chunks (same geometry)
    const __half* bW = g_W1t + ((size_t)e * HDIM + n0 + r) * DDIM + half * 32;
    uint32_t swo[4];
    const uint32_t rowOff = (uint32_t)r * 128 + half * 64;
#pragma unroll
    for (int i = 0; i < 4; i++) swo[i] = SW(rowOff + 16 * i);

    auto issue = [&](int kt) {
        uint32_t dst = sb + OFF_T + (uint32_t)(kt % 3) * STAGE;
        const size_t ko = (size_t)kt * KC;
#pragma unroll
        for (int i = 0; i < 4; i++) {
            CP16(dst + swo[i],         aS + ko + i * 8);
            CP16(dst + B_OFF + swo[i], bW + ko + i * 8);
        }
        CP_COMMIT();
    };

    const int wm = (wid >> 2) * 64, wn = (wid & 3) * 32;
    const int rA = wm + (lane & 7) + ((lane >> 3) & 1) * 8, aSel = (lane >> 4) & 1;
    const int rB = wn + (lane & 7) + ((lane >> 4) & 1) * 8, bSel = (lane >> 3) & 1;

    float acc[4][4][4];
#pragma unroll
    for (int a = 0; a < 4; a++)
#pragma unroll
        for (int bq = 0; bq < 4; bq++)
#pragma unroll
            for (int c = 0; c < 4; c++) acc[a][bq][c] = 0.f;

    const int NS = DDIM / KC;  // 16
    issue(0); issue(1);
    for (int kt = 0; kt < NS; kt++) {
        if (kt == NS - 1) { CP_WAIT0(); } else { CP_WAIT1(); }
        __syncthreads();
        if (kt + 2 < NS) issue(kt + 2);
        mma_stage(sb, kt % 3, rA, aSel, rB, bSel, acc);
        __syncthreads();
    }

    // epilogue: bias + relu -> g_h16
    const int crow = lane >> 2, ccol = (lane & 3) * 2;
#pragma unroll
    for (int mi = 0; mi < 4; mi++)
#pragma unroll
        for (int h = 0; h < 2; h++) {
            const int ml = wm + mi * 16 + crow + h * 8;
            const int entm = sEnt[ml];
            if (entm < 0) continue;
            __half* oh = g_h16 + (size_t)entm * HDIM + n0;
#pragma unroll
            for (int ni = 0; ni < 4; ni++) {
                const int tn = wn + ni * 8 + ccol;
                float v0 = fmaxf(acc[mi][ni][h * 2 + 0] + sBias[tn], 0.f);
                float v1 = fmaxf(acc[mi][ni][h * 2 + 1] + sBias[tn + 1], 0.f);
                *(uint32_t*)(oh + tn) = pkh(__float2half_rn(v0), __float2half_rn(v1));
            }
        }
}

// ---------------- GEMM2: out += w * (h @ W2t^T + b2)  (fused combine) --------
__global__ __launch_bounds__(NTHR, 2)
void gemm2_mma(const float* __restrict__ b2, float* __restrict__ out) {
    const int e = blockIdx.z;
    const int count = g_count[e];
    const int r0 = blockIdx.y * MT;
    if (r0 >= count) return;
    const int n0 = blockIdx.x * NT;

    extern __shared__ char smem[];
    const uint32_t sb = smem_u32(smem);
    const int t = threadIdx.x, wid = t >> 5, lane = t & 31;

    int*   sEnt  = (int*)(smem + OFF_ENT);
    float* sW    = (float*)(smem + OFF_W);
    float* sBias = (float*)(smem + OFF_BIAS);
    if (t < 128) {
        int pos = r0 + t;
        bool ok = (pos < count);
        sEnt[t]  = ok ? g_list[e * B_TOK + pos] : -1;
        sW[t]    = ok ? g_wlist[e * B_TOK + pos] : 0.f;
        sBias[t] = b2[(size_t)e * ODIM + n0 + t];
    }
    __syncthreads();

    const int r = t >> 1;
    const int half = t & 1;
    const int ent = sEnt[r];
    const int row = (ent < 0 ? 0 : ent);
    const __half* aS = g_h16 + (size_t)row * HDIM + half * 32;
    const __half* bW = g_W2t + ((size_t)e * ODIM + n0 + r) * HDIM + half * 32;
    uint32_t swo[4];
    const uint32_t rowOff = (uint32_t)r * 128 + half * 64;
#pragma unroll
    for (int i = 0; i < 4; i++) swo[i] = SW(rowOff + 16 * i);

    auto issue = [&](int kt) {
        uint32_t dst = sb + OFF_T + (uint32_t)(kt % 3) * STAGE;
        const size_t ko = (size_t)kt * KC;
#pragma unroll
        for (int i = 0; i < 4; i++) {
            CP16(dst + swo[i],         aS + ko + i * 8);
            CP16(dst + B_OFF + swo[i], bW + ko + i * 8);
        }
        CP_COMMIT();
    };

    const int wm = (wid >> 2) * 64, wn = (wid & 3) * 32;
    const int rA = wm + (lane & 7) + ((lane >> 3) & 1) * 8, aSel = (lane >> 4) & 1;
    const int rB = wn + (lane & 7) + ((lane >> 4) & 1) * 8, bSel = (lane >> 3) & 1;

    float acc[4][4][4];
#pragma unroll
    for (int a = 0; a < 4; a++)
#pragma unroll
        for (int bq = 0; bq < 4; bq++)
#pragma unroll
            for (int c = 0; c < 4; c++) acc[a][bq][c] = 0.f;

    const int NS = HDIM / KC;  // 32
    issue(0); issue(1);
    for (int kt = 0; kt < NS; kt++) {
        if (kt == NS - 1) { CP_WAIT0(); } else { CP_WAIT1(); }
        __syncthreads();
        if (kt + 2 < NS) issue(kt + 2);
        mma_stage(sb, kt % 3, rA, aSel, rB, bSel, acc);
        __syncthreads();
    }

    // epilogue: atomicAdd w*(acc+bias) into out[token]  (2 adds/element,
    // commutative fp add -> bitwise deterministic)
    const int crow = lane >> 2, ccol = (lane & 3) * 2;
#pragma unroll
    for (int mi = 0; mi < 4; mi++)
#pragma unroll
        for (int h = 0; h < 2; h++) {
            const int ml = wm + mi * 16 + crow + h * 8;
            const int entm = sEnt[ml];
            if (entm < 0) continue;
            const float wt = sW[ml];
            float* op = out + (size_t)(entm >> 1) * ODIM + n0;
#pragma unroll
            for (int ni = 0; ni < 4; ni++) {
                const int tn = wn + ni * 8 + ccol;
                atomicAdd(op + tn,     (acc[mi][ni][h * 2 + 0] + sBias[tn]) * wt);
                atomicAdd(op + tn + 1, (acc[mi][ni][h * 2 + 1] + sBias[tn + 1]) * wt);
            }
        }
}

// ============================ launch =========================================
// Order keeps gemm1 at launch index 3 (ncu profiles index 3).
extern "C" void kernel_launch(void* const* d_in, const int* in_sizes, int n_in,
                              void* d_out, int out_size) {
    const float* x  = (const float*)d_in[0];
    const float* Wg = (const float*)d_in[1];
    const float* bg = (const float*)d_in[2];
    const float* W1 = (const float*)d_in[3];
    const float* b1 = (const float*)d_in[4];
    const float* W2 = (const float*)d_in[5];
    const float* b2 = (const float*)d_in[6];
    float* out = (float*)d_out;

    static int smem_set = 0;
    if (!smem_set) {
        cudaFuncSetAttribute(gemm1_mma, cudaFuncAttributeMaxDynamicSharedMemorySize, SMEM_BYTES);
        cudaFuncSetAttribute(gemm2_mma, cudaFuncAttributeMaxDynamicSharedMemorySize, SMEM_BYTES);
        smem_set = 1;
    }

    convW1_kernel<<<dim3(HDIM / 32, DDIM / 32, NEXP), dim3(32, 8)>>>(W1);
    zero_counts_kernel<<<1, 32>>>();
    gate_kernel<<<B_TOK / 8, 256>>>(x, Wg, bg, out);

    gemm1_mma<<<dim3(HDIM / NT, B_TOK / MT, NEXP), NTHR, SMEM_BYTES>>>(b1);

    convW2_kernel<<<dim3(ODIM / 32, HDIM / 32, NEXP), dim3(32, 8)>>>(W2);
    gemm2_mma<<<dim3(ODIM / NT, B_TOK / MT, NEXP), NTHR, SMEM_BYTES>>>(b2, out);
}

// round 16
// speedup vs baseline: 1.0745x; 1.0745x over previous
#include <cuda_runtime.h>
#include <cuda_fp16.h>
#include <cstdint>

#define B_TOK 8192
#define DDIM  1024
#define HDIM  2048
#define ODIM  1024
#define NEXP  8

#define MT 128
#define NT 256
#define KC 64
#define NTHR 512

// ---------------- scratch (device globals: allocation-free rule) -------------
__device__ int   g_count[NEXP];
__device__ int   g_list[NEXP * B_TOK];     // entry = token*2 + slot
__device__ float g_wlist[NEXP * B_TOK];
__device__ alignas(128) __half g_x16[(size_t)B_TOK * DDIM];
__device__ alignas(128) __half g_W1t[(size_t)NEXP * HDIM * DDIM];  // [E][H][D] fp16
__device__ alignas(128) __half g_W2t[(size_t)NEXP * ODIM * HDIM];  // [E][O][H] fp16
__device__ alignas(128) __half g_h16[(size_t)2 * B_TOK * HDIM];    // [16384][H]

// ---------------- helpers ----------------------------------------------------
__device__ __forceinline__ uint32_t smem_u32(const void* p) {
    uint32_t a;
    asm("{ .reg .u64 t; cvta.to.shared.u64 t, %1; cvt.u32.u64 %0, t; }"
        : "=r"(a) : "l"(p));
    return a;
}
#define SW(o) ((o) ^ (((o) >> 3) & 0x70))

__device__ __forceinline__ void ldsm4(uint32_t* r, uint32_t a) {
    asm volatile("ldmatrix.sync.aligned.m8n8.x4.shared.b16 {%0,%1,%2,%3}, [%4];"
        : "=r"(r[0]), "=r"(r[1]), "=r"(r[2]), "=r"(r[3]) : "r"(a));
}
__device__ __forceinline__ void mma16816(float* c, const uint32_t* a, const uint32_t* b) {
    asm volatile("mma.sync.aligned.m16n8k16.row.col.f32.f16.f16.f32 "
        "{%0,%1,%2,%3}, {%4,%5,%6,%7}, {%8,%9}, {%0,%1,%2,%3};"
        : "+f"(c[0]), "+f"(c[1]), "+f"(c[2]), "+f"(c[3])
        : "r"(a[0]), "r"(a[1]), "r"(a[2]), "r"(a[3]), "r"(b[0]), "r"(b[1]));
}
#define CP16(dst, src) \
    asm volatile("cp.async.cg.shared.global [%0], [%1], 16;" :: "r"(dst), "l"(src))
#define CP_COMMIT() asm volatile("cp.async.commit_group;" ::: "memory")
#define CP_WAIT2()  asm volatile("cp.async.wait_group 2;" ::: "memory")
#define CP_WAIT1()  asm volatile("cp.async.wait_group 1;" ::: "memory")
#define CP_WAIT0()  asm volatile("cp.async.wait_group 0;" ::: "memory")

__device__ __forceinline__ uint32_t pkh(__half a, __half b) {
    return (uint32_t)__half_as_ushort(a) | ((uint32_t)__half_as_ushort(b) << 16);
}

// ---------------- SMEM layout ------------------------------------------------
// [0,512) sEnt  [512,1024) sW  [1024,2048) sBias (256 floats)
// [2048, +4*48K): 4 pipeline stages, each [A 16K | B 32K]
#define OFF_ENT  0
#define OFF_W    512
#define OFF_BIAS 1024
#define OFF_T    2048
#define B_OFF    16384
#define STAGE    49152
#define SMEM_BYTES (OFF_T + 4 * STAGE)   // 198656

// ============================ gating (+x cast, +out zeroing fused) ===========
__global__ void zero_counts_kernel() {
    if (threadIdx.x < NEXP) g_count[threadIdx.x] = 0;
}

__global__ void gate_kernel(const float* __restrict__ x,
                            const float* __restrict__ Wg,
                            const float* __restrict__ bg,
                            float* __restrict__ out) {
    int gw   = (blockIdx.x * blockDim.x + threadIdx.x) >> 5;
    int lane = threadIdx.x & 31;
    if (gw >= B_TOK) return;
    {
        float4* orow = reinterpret_cast<float4*>(out + (size_t)gw * ODIM);
        float4 z = make_float4(0.f, 0.f, 0.f, 0.f);
#pragma unroll
        for (int i = 0; i < ODIM / 4 / 32; i++)
            orow[lane + 32 * i] = z;
    }
    const float* xr = x + (size_t)gw * DDIM;
    __half* xo = g_x16 + (size_t)gw * DDIM;
    float acc[NEXP];
#pragma unroll
    for (int e = 0; e < NEXP; e++) acc[e] = 0.f;
    for (int d = lane; d < DDIM; d += 32) {
        float xv = xr[d];
        xo[d] = __float2half_rn(xv);
        const float4* w4 = reinterpret_cast<const float4*>(Wg + (size_t)d * NEXP);
        float4 w0 = w4[0], w1 = w4[1];
        acc[0] += xv * w0.x; acc[1] += xv * w0.y;
        acc[2] += xv * w0.z; acc[3] += xv * w0.w;
        acc[4] += xv * w1.x; acc[5] += xv * w1.y;
        acc[6] += xv * w1.z; acc[7] += xv * w1.w;
    }
#pragma unroll
    for (int off = 16; off; off >>= 1)
#pragma unroll
        for (int e = 0; e < NEXP; e++)
            acc[e] += __shfl_xor_sync(0xFFFFFFFFu, acc[e], off);
    if (lane == 0) {
        float s[NEXP];
#pragma unroll
        for (int e = 0; e < NEXP; e++) s[e] = acc[e] + bg[e];
        float M = s[0];
#pragma unroll
        for (int e = 1; e < NEXP; e++) M = fmaxf(M, s[e]);
        float p[NEXP], Z = 0.f;
#pragma unroll
        for (int e = 0; e < NEXP; e++) { p[e] = expf(s[e] - M); Z += p[e]; }
        int i1 = 0;
#pragma unroll
        for (int e = 1; e < NEXP; e++) if (s[e] > s[i1]) i1 = e;
        int i2 = -1;
#pragma unroll
        for (int e = 0; e < NEXP; e++)
            if (e != i1 && (i2 < 0 || s[e] > s[i2])) i2 = e;
        float denom = p[i1] + p[i2] + 1e-8f * Z;
        float w1 = p[i1] / denom;
        float w2 = p[i2] / denom;
        int pos1 = atomicAdd(&g_count[i1], 1);
        g_list[i1 * B_TOK + pos1]  = gw * 2 + 0;
        g_wlist[i1 * B_TOK + pos1] = w1;
        int pos2 = atomicAdd(&g_count[i2], 1);
        g_list[i2 * B_TOK + pos2]  = gw * 2 + 1;
        g_wlist[i2 * B_TOK + pos2] = w2;
    }
}

// ============ weight transpose + fp16 cast ===================================
__global__ void convW1_kernel(const float* __restrict__ W1) {
    __shared__ float ts[32][33];
    int e = blockIdx.z;
    int h0 = blockIdx.x * 32, d0 = blockIdx.y * 32;
    int tx = threadIdx.x, ty = threadIdx.y;
    const float* src = W1 + ((size_t)e * DDIM + d0) * HDIM + h0;
#pragma unroll
    for (int j = 0; j < 4; j++)
        ts[ty + 8 * j][tx] = src[(size_t)(ty + 8 * j) * HDIM + tx];
    __syncthreads();
    int t = ty * 32 + tx;
    int r = t >> 3;
    int c = t & 7;
    __half v0 = __float2half_rn(ts[4 * c + 0][r]);
    __half v1 = __float2half_rn(ts[4 * c + 1][r]);
    __half v2 = __float2half_rn(ts[4 * c + 2][r]);
    __half v3 = __float2half_rn(ts[4 * c + 3][r]);
    *reinterpret_cast<uint2*>(g_W1t + ((size_t)e * HDIM + h0 + r) * DDIM + d0 + 4 * c) =
        make_uint2(pkh(v0, v1), pkh(v2, v3));
}

__global__ void convW2_kernel(const float* __restrict__ W2) {
    __shared__ float ts[32][33];
    int e = blockIdx.z;
    int o0 = blockIdx.x * 32, h0 = blockIdx.y * 32;
    int tx = threadIdx.x, ty = threadIdx.y;
    const float* src = W2 + ((size_t)e * HDIM + h0) * ODIM + o0;
#pragma unroll
    for (int j = 0; j < 4; j++)
        ts[ty + 8 * j][tx] = src[(size_t)(ty + 8 * j) * ODIM + tx];
    __syncthreads();
    int t = ty * 32 + tx;
    int r = t >> 3;
    int c = t & 7;
    __half v0 = __float2half_rn(ts[4 * c + 0][r]);
    __half v1 = __float2half_rn(ts[4 * c + 1][r]);
    __half v2 = __float2half_rn(ts[4 * c + 2][r]);
    __half v3 = __float2half_rn(ts[4 * c + 3][r]);
    *reinterpret_cast<uint2*>(g_W2t + ((size_t)e * ODIM + o0 + r) * HDIM + h0 + 4 * c) =
        make_uint2(pkh(v0, v1), pkh(v2, v3));
}

// ============================ GEMM core ======================================
// 16 warps (2 M x 8 N); warp tile 64x32.
// Rolling fragment pipeline: 16 flattened (k16,mi) units; unit u+1's ldsm
// issue between unit u's 4 mma -> ldsm latency covered, no ldsm bursts.
// af rolls 2-deep (8 regs), bf double-buffers per k16 (16 regs): net 0 vs R14.
__device__ __forceinline__ void mma_stage(uint32_t sb, int st,
                                          int rA, int aSel, int rB, int bSel,
                                          float acc[4][4][4]) {
    const uint32_t AB = sb + OFF_T + (uint32_t)st * STAGE;
    const uint32_t BB = AB + B_OFF;
    uint32_t af[2][4], bf[2][2][4];
    // prologue: bf for k16=0, af for unit 0 (k16=0, mi=0)
    ldsm4(bf[0][0], BB + SW((uint32_t)rB * 128 + bSel * 16));
    ldsm4(bf[0][1], BB + SW((uint32_t)(rB + 16) * 128 + bSel * 16));
    ldsm4(af[0],    AB + SW((uint32_t)rA * 128 + aSel * 16));
#pragma unroll
    for (int u = 0; u < 16; u++) {
        const int k16 = u >> 2, mi = u & 3;
        const int un = u + 1;
        if (un < 16) {
            const int nk = un >> 2, nmi = un & 3;
            const uint32_t nkb = (uint32_t)nk * 32;
            if (nmi == 0) {
                ldsm4(bf[nk & 1][0], BB + SW((uint32_t)rB * 128 + nkb + bSel * 16));
                ldsm4(bf[nk & 1][1], BB + SW((uint32_t)(rB + 16) * 128 + nkb + bSel * 16));
            }
            ldsm4(af[un & 1],
                  AB + SW((uint32_t)(rA + nmi * 16) * 128 + nkb + aSel * 16));
        }
        const uint32_t* a  = af[u & 1];
        const uint32_t* b0 = bf[k16 & 1][0];
        const uint32_t* b1 = bf[k16 & 1][1];
        mma16816(acc[mi][0], a, &b0[0]);
        mma16816(acc[mi][1], a, &b0[2]);
        mma16816(acc[mi][2], a, &b1[0]);
        mma16816(acc[mi][3], a, &b1[2]);
    }
}

// ---------------- GEMM1: h = relu(x_g @ W1t^T + b1) --------------------------
__global__ __launch_bounds__(NTHR, 1)
void gemm1_mma(const float* __restrict__ b1) {
    const int e = blockIdx.z;
    const int count = g_count[e];
    const int r0 = blockIdx.y * MT;
    if (r0 >= count) return;
    const int n0 = blockIdx.x * NT;

    extern __shared__ char smem[];
    const uint32_t sb = smem_u32(smem);
    const int t = threadIdx.x, wid = t >> 5, lane = t & 31;

    int*   sEnt  = (int*)(smem + OFF_ENT);
    float* sBias = (float*)(smem + OFF_BIAS);
    if (t < 128) {
        int pos = r0 + t;
        sEnt[t]  = (pos < count) ? g_list[e * B_TOK + pos] : -1;
    }
    if (t < 256) sBias[t] = b1[(size_t)e * HDIM + n0 + t];
    __syncthreads();

    // A copy: row = t>>2 (0..127), quarter q = t&3 (32B each), 2 chunks
    const int ar = t >> 2;
    const int q = t & 3;
    const int ent = sEnt[ar];
    const int tok = (ent < 0 ? 0 : ent) >> 1;
    const __half* aS = g_x16 + (size_t)tok * DDIM + q * 16;
    uint32_t aswo[2];
#pragma unroll
    for (int i = 0; i < 2; i++) aswo[i] = SW((uint32_t)ar * 128 + q * 32 + 16 * i);
    // B copy: row = t>>1 (0..255), half hb = t&1 (64B), 4 chunks
    const int br = t >> 1;
    const int hb = t & 1;
    const __half* bW = g_W1t + ((size_t)e * HDIM + n0 + br) * DDIM + hb * 32;
    uint32_t bswo[4];
#pragma unroll
    for (int i = 0; i < 4; i++) bswo[i] = SW((uint32_t)br * 128 + hb * 64 + 16 * i);

    auto issue = [&](int kt) {
        uint32_t dst = sb + OFF_T + (uint32_t)(kt & 3) * STAGE;
        const size_t ko = (size_t)kt * KC;
#pragma unroll
        for (int i = 0; i < 2; i++)
            CP16(dst + aswo[i], aS + ko + i * 8);
#pragma unroll
        for (int i = 0; i < 4; i++)
            CP16(dst + B_OFF + bswo[i], bW + ko + i * 8);
        CP_COMMIT();
    };

    const int wm = (wid >> 3) * 64, wn = (wid & 7) * 32;
    const int rA = wm + (lane & 7) + ((lane >> 3) & 1) * 8, aSel = (lane >> 4) & 1;
    const int rB = wn + (lane & 7) + ((lane >> 4) & 1) * 8, bSel = (lane >> 3) & 1;

    float acc[4][4][4];
#pragma unroll
    for (int a = 0; a < 4; a++)
#pragma unroll
        for (int bq = 0; bq < 4; bq++)
#pragma unroll
            for (int c = 0; c < 4; c++) acc[a][bq][c] = 0.f;

    const int NS = DDIM / KC;  // 16
    issue(0); issue(1); issue(2);
    for (int kt = 0; kt < NS; kt++) {
        if (kt <= NS - 3)      { CP_WAIT2(); }
        else if (kt == NS - 2) { CP_WAIT1(); }
        else                   { CP_WAIT0(); }
        __syncthreads();
        if (kt + 3 < NS) issue(kt + 3);
        mma_stage(sb, kt & 3, rA, aSel, rB, bSel, acc);
    }

    // epilogue: bias + relu -> g_h16
    const int crow = lane >> 2, ccol = (lane & 3) * 2;
#pragma unroll
    for (int mi = 0; mi < 4; mi++)
#pragma unroll
        for (int h = 0; h < 2; h++) {
            const int ml = wm + mi * 16 + crow + h * 8;
            const int entm = sEnt[ml];
            if (entm < 0) continue;
            __half* oh = g_h16 + (size_t)entm * HDIM + n0;
#pragma unroll
            for (int ni = 0; ni < 4; ni++) {
                const int tn = wn + ni * 8 + ccol;
                float v0 = fmaxf(acc[mi][ni][h * 2 + 0] + sBias[tn], 0.f);
                float v1 = fmaxf(acc[mi][ni][h * 2 + 1] + sBias[tn + 1], 0.f);
                *(uint32_t*)(oh + tn) = pkh(__float2half_rn(v0), __float2half_rn(v1));
            }
        }
}

// ---------------- GEMM2: out += w * (h @ W2t^T + b2)  (fused combine) --------
__global__ __launch_bounds__(NTHR, 1)
void gemm2_mma(const float* __restrict__ b2, float* __restrict__ out) {
    const int e = blockIdx.z;
    const int count = g_count[e];
    const int r0 = blockIdx.y * MT;
    if (r0 >= count) return;
    const int n0 = blockIdx.x * NT;

    extern __shared__ char smem[];
    const uint32_t sb = smem_u32(smem);
    const int t = threadIdx.x, wid = t >> 5, lane = t & 31;

    int*   sEnt  = (int*)(smem + OFF_ENT);
    float* sW    = (float*)(smem + OFF_W);
    float* sBias = (float*)(smem + OFF_BIAS);
    if (t < 128) {
        int pos = r0 + t;
        bool ok = (pos < count);
        sEnt[t]  = ok ? g_list[e * B_TOK + pos] : -1;
        sW[t]    = ok ? g_wlist[e * B_TOK + pos] : 0.f;
    }
    if (t < 256) sBias[t] = b2[(size_t)e * ODIM + n0 + t];
    __syncthreads();

    const int ar = t >> 2;
    const int q = t & 3;
    const int ent = sEnt[ar];
    const int row = (ent < 0 ? 0 : ent);
    const __half* aS = g_h16 + (size_t)row * HDIM + q * 16;
    uint32_t aswo[2];
#pragma unroll
    for (int i = 0; i < 2; i++) aswo[i] = SW((uint32_t)ar * 128 + q * 32 + 16 * i);
    const int br = t >> 1;
    const int hb = t & 1;
    const __half* bW = g_W2t + ((size_t)e * ODIM + n0 + br) * HDIM + hb * 32;
    uint32_t bswo[4];
#pragma unroll
    for (int i = 0; i < 4; i++) bswo[i] = SW((uint32_t)br * 128 + hb * 64 + 16 * i);

    auto issue = [&](int kt) {
        uint32_t dst = sb + OFF_T + (uint32_t)(kt & 3) * STAGE;
        const size_t ko = (size_t)kt * KC;
#pragma unroll
        for (int i = 0; i < 2; i++)
            CP16(dst + aswo[i], aS + ko + i * 8);
#pragma unroll
        for (int i = 0; i < 4; i++)
            CP16(dst + B_OFF + bswo[i], bW + ko + i * 8);
        CP_COMMIT();
    };

    const int wm = (wid >> 3) * 64, wn = (wid & 7) * 32;
    const int rA = wm + (lane & 7) + ((lane >> 3) & 1) * 8, aSel = (lane >> 4) & 1;
    const int rB = wn + (lane & 7) + ((lane >> 4) & 1) * 8, bSel = (lane >> 3) & 1;

    float acc[4][4][4];
#pragma unroll
    for (int a = 0; a < 4; a++)
#pragma unroll
        for (int bq = 0; bq < 4; bq++)
#pragma unroll
            for (int c = 0; c < 4; c++) acc[a][bq][c] = 0.f;

    const int NS = HDIM / KC;  // 32
    issue(0); issue(1); issue(2);
    for (int kt = 0; kt < NS; kt++) {
        if (kt <= NS - 3)      { CP_WAIT2(); }
        else if (kt == NS - 2) { CP_WAIT1(); }
        else                   { CP_WAIT0(); }
        __syncthreads();
        if (kt + 3 < NS) issue(kt + 3);
        mma_stage(sb, kt & 3, rA, aSel, rB, bSel, acc);
    }

    // epilogue: atomicAdd w*(acc+bias) into out[token]  (2 adds/element,
    // commutative fp add -> bitwise deterministic)
    const int crow = lane >> 2, ccol = (lane & 3) * 2;
#pragma unroll
    for (int mi = 0; mi < 4; mi++)
#pragma unroll
        for (int h = 0; h < 2; h++) {
            const int ml = wm + mi * 16 + crow + h * 8;
            const int entm = sEnt[ml];
            if (entm < 0) continue;
            const float wt = sW[ml];
            float* op = out + (size_t)(entm >> 1) * ODIM + n0;
#pragma unroll
            for (int ni = 0; ni < 4; ni++) {
                const int tn = wn + ni * 8 + ccol;
                atomicAdd(op + tn,     (acc[mi][ni][h * 2 + 0] + sBias[tn]) * wt);
                atomicAdd(op + tn + 1, (acc[mi][ni][h * 2 + 1] + sBias[tn + 1]) * wt);
            }
        }
}

// ============================ launch =========================================
// Order keeps gemm1 at launch index 3 (ncu profiles index 3).
extern "C" void kernel_launch(void* const* d_in, const int* in_sizes, int n_in,
                              void* d_out, int out_size) {
    const float* x  = (const float*)d_in[0];
    const float* Wg = (const float*)d_in[1];
    const float* bg = (const float*)d_in[2];
    const float* W1 = (const float*)d_in[3];
    const float* b1 = (const float*)d_in[4];
    const float* W2 = (const float*)d_in[5];
    const float* b2 = (const float*)d_in[6];
    float* out = (float*)d_out;

    static int smem_set = 0;
    if (!smem_set) {
        cudaFuncSetAttribute(gemm1_mma, cudaFuncAttributeMaxDynamicSharedMemorySize, SMEM_BYTES);
        cudaFuncSetAttribute(gemm2_mma, cudaFuncAttributeMaxDynamicSharedMemorySize, SMEM_BYTES);
        smem_set = 1;
    }

    convW1_kernel<<<dim3(HDIM / 32, DDIM / 32, NEXP), dim3(32, 8)>>>(W1);
    zero_counts_kernel<<<1, 32>>>();
    gate_kernel<<<B_TOK / 8, 256>>>(x, Wg, bg, out);

    gemm1_mma<<<dim3(HDIM / NT, B_TOK / MT, NEXP), NTHR, SMEM_BYTES>>>(b1);

    convW2_kernel<<<dim3(ODIM / 32, HDIM / 32, NEXP), dim3(32, 8)>>>(W2);
    gemm2_mma<<<dim3(ODIM / NT, B_TOK / MT, NEXP), NTHR, SMEM_BYTES>>>(b2, out);
}

// round 17
// speedup vs baseline: 1.1123x; 1.0351x over previous
#include <cuda_runtime.h>
#include <cuda_fp16.h>
#include <cstdint>

#define B_TOK 8192
#define DDIM  1024
#define HDIM  2048
#define ODIM  1024
#define NEXP  8

#define MT 192
#define NT 128
#define KC 64
#define NTHR 768

// ---------------- scratch (device globals: allocation-free rule) -------------
__device__ int   g_count[NEXP];
__device__ int   g_list[NEXP * B_TOK];     // entry = token*2 + slot
__device__ float g_wlist[NEXP * B_TOK];
__device__ alignas(128) __half g_x16[(size_t)B_TOK * DDIM];
__device__ alignas(128) __half g_W1t[(size_t)NEXP * HDIM * DDIM];  // [E][H][D] fp16
__device__ alignas(128) __half g_W2t[(size_t)NEXP * ODIM * HDIM];  // [E][O][H] fp16
__device__ alignas(128) __half g_h16[(size_t)2 * B_TOK * HDIM];    // [16384][H]

// ---------------- helpers ----------------------------------------------------
__device__ __forceinline__ uint32_t smem_u32(const void* p) {
    uint32_t a;
    asm("{ .reg .u64 t; cvta.to.shared.u64 t, %1; cvt.u32.u64 %0, t; }"
        : "=r"(a) : "l"(p));
    return a;
}
#define SW(o) ((o) ^ (((o) >> 3) & 0x70))

__device__ __forceinline__ void ldsm4(uint32_t* r, uint32_t a) {
    asm volatile("ldmatrix.sync.aligned.m8n8.x4.shared.b16 {%0,%1,%2,%3}, [%4];"
        : "=r"(r[0]), "=r"(r[1]), "=r"(r[2]), "=r"(r[3]) : "r"(a));
}
__device__ __forceinline__ void mma16816(float* c, const uint32_t* a, const uint32_t* b) {
    asm volatile("mma.sync.aligned.m16n8k16.row.col.f32.f16.f16.f32 "
        "{%0,%1,%2,%3}, {%4,%5,%6,%7}, {%8,%9}, {%0,%1,%2,%3};"
        : "+f"(c[0]), "+f"(c[1]), "+f"(c[2]), "+f"(c[3])
        : "r"(a[0]), "r"(a[1]), "r"(a[2]), "r"(a[3]), "r"(b[0]), "r"(b[1]));
}
#define CP16(dst, src) \
    asm volatile("cp.async.cg.shared.global [%0], [%1], 16;" :: "r"(dst), "l"(src))
#define CP_COMMIT() asm volatile("cp.async.commit_group;" ::: "memory")
#define CP_WAIT2()  asm volatile("cp.async.wait_group 2;" ::: "memory")
#define CP_WAIT1()  asm volatile("cp.async.wait_group 1;" ::: "memory")
#define CP_WAIT0()  asm volatile("cp.async.wait_group 0;" ::: "memory")

__device__ __forceinline__ uint32_t pkh(__half a, __half b) {
    return (uint32_t)__half_as_ushort(a) | ((uint32_t)__half_as_ushort(b) << 16);
}

// ---------------- SMEM layout ------------------------------------------------
// [0,768) sEnt(192)  [768,1536) sW(192)  [1536,2048) sBias(128)
// [2048, +4*40960): 4 pipeline stages, each [A 24K | B 16K]
#define OFF_ENT  0
#define OFF_W    768
#define OFF_BIAS 1536
#define OFF_T    2048
#define B_OFF    24576
#define STAGE    40960
#define SMEM_BYTES (OFF_T + 4 * STAGE)   // 165888

// ============================ gating (+x cast, +out zeroing fused) ===========
__global__ void zero_counts_kernel() {
    if (threadIdx.x < NEXP) g_count[threadIdx.x] = 0;
}

__global__ void gate_kernel(const float* __restrict__ x,
                            const float* __restrict__ Wg,
                            const float* __restrict__ bg,
                            float* __restrict__ out) {
    int gw   = (blockIdx.x * blockDim.x + threadIdx.x) >> 5;
    int lane = threadIdx.x & 31;
    if (gw >= B_TOK) return;
    {
        float4* orow = reinterpret_cast<float4*>(out + (size_t)gw * ODIM);
        float4 z = make_float4(0.f, 0.f, 0.f, 0.f);
#pragma unroll
        for (int i = 0; i < ODIM / 4 / 32; i++)
            orow[lane + 32 * i] = z;
    }
    const float* xr = x + (size_t)gw * DDIM;
    __half* xo = g_x16 + (size_t)gw * DDIM;
    float acc[NEXP];
#pragma unroll
    for (int e = 0; e < NEXP; e++) acc[e] = 0.f;
    for (int d = lane; d < DDIM; d += 32) {
        float xv = xr[d];
        xo[d] = __float2half_rn(xv);
        const float4* w4 = reinterpret_cast<const float4*>(Wg + (size_t)d * NEXP);
        float4 w0 = w4[0], w1 = w4[1];
        acc[0] += xv * w0.x; acc[1] += xv * w0.y;
        acc[2] += xv * w0.z; acc[3] += xv * w0.w;
        acc[4] += xv * w1.x; acc[5] += xv * w1.y;
        acc[6] += xv * w1.z; acc[7] += xv * w1.w;
    }
#pragma unroll
    for (int off = 16; off; off >>= 1)
#pragma unroll
        for (int e = 0; e < NEXP; e++)
            acc[e] += __shfl_xor_sync(0xFFFFFFFFu, acc[e], off);
    if (lane == 0) {
        float s[NEXP];
#pragma unroll
        for (int e = 0; e < NEXP; e++) s[e] = acc[e] + bg[e];
        float M = s[0];
#pragma unroll
        for (int e = 1; e < NEXP; e++) M = fmaxf(M, s[e]);
        float p[NEXP], Z = 0.f;
#pragma unroll
        for (int e = 0; e < NEXP; e++) { p[e] = expf(s[e] - M); Z += p[e]; }
        int i1 = 0;
#pragma unroll
        for (int e = 1; e < NEXP; e++) if (s[e] > s[i1]) i1 = e;
        int i2 = -1;
#pragma unroll
        for (int e = 0; e < NEXP; e++)
            if (e != i1 && (i2 < 0 || s[e] > s[i2])) i2 = e;
        float denom = p[i1] + p[i2] + 1e-8f * Z;
        float w1 = p[i1] / denom;
        float w2 = p[i2] / denom;
        int pos1 = atomicAdd(&g_count[i1], 1);
        g_list[i1 * B_TOK + pos1]  = gw * 2 + 0;
        g_wlist[i1 * B_TOK + pos1] = w1;
        int pos2 = atomicAdd(&g_count[i2], 1);
        g_list[i2 * B_TOK + pos2]  = gw * 2 + 1;
        g_wlist[i2 * B_TOK + pos2] = w2;
    }
}

// ============ weight transpose + fp16 cast ===================================
__global__ void convW1_kernel(const float* __restrict__ W1) {
    __shared__ float ts[32][33];
    int e = blockIdx.z;
    int h0 = blockIdx.x * 32, d0 = blockIdx.y * 32;
    int tx = threadIdx.x, ty = threadIdx.y;
    const float* src = W1 + ((size_t)e * DDIM + d0) * HDIM + h0;
#pragma unroll
    for (int j = 0; j < 4; j++)
        ts[ty + 8 * j][tx] = src[(size_t)(ty + 8 * j) * HDIM + tx];
    __syncthreads();
    int t = ty * 32 + tx;
    int r = t >> 3;
    int c = t & 7;
    __half v0 = __float2half_rn(ts[4 * c + 0][r]);
    __half v1 = __float2half_rn(ts[4 * c + 1][r]);
    __half v2 = __float2half_rn(ts[4 * c + 2][r]);
    __half v3 = __float2half_rn(ts[4 * c + 3][r]);
    *reinterpret_cast<uint2*>(g_W1t + ((size_t)e * HDIM + h0 + r) * DDIM + d0 + 4 * c) =
        make_uint2(pkh(v0, v1), pkh(v2, v3));
}

__global__ void convW2_kernel(const float* __restrict__ W2) {
    __shared__ float ts[32][33];
    int e = blockIdx.z;
    int o0 = blockIdx.x * 32, h0 = blockIdx.y * 32;
    int tx = threadIdx.x, ty = threadIdx.y;
    const float* src = W2 + ((size_t)e * HDIM + h0) * ODIM + o0;
#pragma unroll
    for (int j = 0; j < 4; j++)
        ts[ty + 8 * j][tx] = src[(size_t)(ty + 8 * j) * ODIM + tx];
    __syncthreads();
    int t = ty * 32 + tx;
    int r = t >> 3;
    int c = t & 7;
    __half v0 = __float2half_rn(ts[4 * c + 0][r]);
    __half v1 = __float2half_rn(ts[4 * c + 1][r]);
    __half v2 = __float2half_rn(ts[4 * c + 2][r]);
    __half v3 = __float2half_rn(ts[4 * c + 3][r]);
    *reinterpret_cast<uint2*>(g_W2t + ((size_t)e * ODIM + o0 + r) * HDIM + h0 + 4 * c) =
        make_uint2(pkh(v0, v1), pkh(v2, v3));
}

// ============================ GEMM core ======================================
// 24 warps (6 M x 4 N); warp tile 32x32 -> acc 32 regs, 6 warps/SMSP.
__device__ __forceinline__ void mma_stage(uint32_t sb, int st,
                                          int rA, int aSel, int rB, int bSel,
                                          float acc[2][4][4]) {
    const uint32_t AB = sb + OFF_T + (uint32_t)st * STAGE;
    const uint32_t BB = AB + B_OFF;
#pragma unroll
    for (int k16 = 0; k16 < 4; k16++) {
        const uint32_t kb = (uint32_t)k16 * 32;
        uint32_t bf[2][4], af[2][4];
        ldsm4(bf[0], BB + SW((uint32_t)rB * 128 + kb + bSel * 16));
        ldsm4(bf[1], BB + SW((uint32_t)(rB + 16) * 128 + kb + bSel * 16));
        ldsm4(af[0], AB + SW((uint32_t)rA * 128 + kb + aSel * 16));
        ldsm4(af[1], AB + SW((uint32_t)(rA + 16) * 128 + kb + aSel * 16));
#pragma unroll
        for (int mi = 0; mi < 2; mi++)
#pragma unroll
            for (int ni = 0; ni < 4; ni++)
                mma16816(acc[mi][ni], af[mi], &bf[ni >> 1][(ni & 1) * 2]);
    }
}

// ---------------- GEMM1: h = relu(x_g @ W1t^T + b1) --------------------------
__global__ __launch_bounds__(NTHR, 1)
void gemm1_mma(const float* __restrict__ b1) {
    const int e = blockIdx.z;
    const int count = g_count[e];
    const int r0 = blockIdx.y * MT;
    if (r0 >= count) return;
    const int n0 = blockIdx.x * NT;

    extern __shared__ char smem[];
    const uint32_t sb = smem_u32(smem);
    const int t = threadIdx.x, wid = t >> 5, lane = t & 31;

    int*   sEnt  = (int*)(smem + OFF_ENT);
    float* sBias = (float*)(smem + OFF_BIAS);
    if (t < MT) {
        int pos = r0 + t;
        sEnt[t]  = (pos < count) ? g_list[e * B_TOK + pos] : -1;
    }
    if (t < NT) sBias[t] = b1[(size_t)e * HDIM + n0 + t];
    __syncthreads();

    // A copy: 192 rows x 128B = 1536 chunks; thread t -> chunks 2t,2t+1
    const int ar = t >> 2;          // 0..191
    const int q = t & 3;
    const int ent = sEnt[ar];
    const int tok = (ent < 0 ? 0 : ent) >> 1;
    const __half* aS = g_x16 + (size_t)tok * DDIM + q * 16;
    uint32_t aswo[2];
#pragma unroll
    for (int i = 0; i < 2; i++) aswo[i] = SW((uint32_t)ar * 128 + q * 32 + 16 * i);
    // B copy: 128 rows x 128B = 1024 chunks; thread t -> chunk t; t<256 also 768+t
    const int br1 = t >> 3, bo1 = (t & 7) * 16;
    const __half* bW = g_W1t + ((size_t)e * HDIM + n0) * DDIM;
    const uint32_t bswo1 = SW((uint32_t)br1 * 128 + bo1);
    const int br2 = 96 + (t >> 3);
    const uint32_t bswo2 = SW((uint32_t)br2 * 128 + bo1);

    auto issue = [&](int kt) {
        uint32_t dst = sb + OFF_T + (uint32_t)(kt & 3) * STAGE;
        const size_t ko = (size_t)kt * KC;
#pragma unroll
        for (int i = 0; i < 2; i++)
            CP16(dst + aswo[i], aS + ko + i * 8);
        CP16(dst + B_OFF + bswo1, bW + (size_t)br1 * DDIM + ko + bo1 / 2);
        if (t < 256)
            CP16(dst + B_OFF + bswo2, bW + (size_t)br2 * DDIM + ko + bo1 / 2);
        CP_COMMIT();
    };

    const int wm = (wid >> 2) * 32, wn = (wid & 3) * 32;
    const int rA = wm + (lane & 7) + ((lane >> 3) & 1) * 8, aSel = (lane >> 4) & 1;
    const int rB = wn + (lane & 7) + ((lane >> 4) & 1) * 8, bSel = (lane >> 3) & 1;

    float acc[2][4][4];
#pragma unroll
    for (int a = 0; a < 2; a++)
#pragma unroll
        for (int bq = 0; bq < 4; bq++)
#pragma unroll
            for (int c = 0; c < 4; c++) acc[a][bq][c] = 0.f;

    const int NS = DDIM / KC;  // 16
    issue(0); issue(1); issue(2);
    for (int kt = 0; kt < NS; kt++) {
        if (kt <= NS - 3)      { CP_WAIT2(); }
        else if (kt == NS - 2) { CP_WAIT1(); }
        else                   { CP_WAIT0(); }
        __syncthreads();
        if (kt + 3 < NS) issue(kt + 3);
        mma_stage(sb, kt & 3, rA, aSel, rB, bSel, acc);
    }

    // epilogue: bias + relu -> g_h16
    const int crow = lane >> 2, ccol = (lane & 3) * 2;
#pragma unroll
    for (int mi = 0; mi < 2; mi++)
#pragma unroll
        for (int h = 0; h < 2; h++) {
            const int ml = wm + mi * 16 + crow + h * 8;
            const int entm = sEnt[ml];
            if (entm < 0) continue;
            __half* oh = g_h16 + (size_t)entm * HDIM + n0;
#pragma unroll
            for (int ni = 0; ni < 4; ni++) {
                const int tn = wn + ni * 8 + ccol;
                float v0 = fmaxf(acc[mi][ni][h * 2 + 0] + sBias[tn], 0.f);
                float v1 = fmaxf(acc[mi][ni][h * 2 + 1] + sBias[tn + 1], 0.f);
                *(uint32_t*)(oh + tn) = pkh(__float2half_rn(v0), __float2half_rn(v1));
            }
        }
}

// ---------------- GEMM2: out += w * (h @ W2t^T + b2)  (fused combine) --------
__global__ __launch_bounds__(NTHR, 1)
void gemm2_mma(const float* __restrict__ b2, float* __restrict__ out) {
    const int e = blockIdx.z;
    const int count = g_count[e];
    const int r0 = blockIdx.y * MT;
    if (r0 >= count) return;
    const int n0 = blockIdx.x * NT;

    extern __shared__ char smem[];
    const uint32_t sb = smem_u32(smem);
    const int t = threadIdx.x, wid = t >> 5, lane = t & 31;

    int*   sEnt  = (int*)(smem + OFF_ENT);
    float* sW    = (float*)(smem + OFF_W);
    float* sBias = (float*)(smem + OFF_BIAS);
    if (t < MT) {
        int pos = r0 + t;
        bool ok = (pos < count);
        sEnt[t]  = ok ? g_list[e * B_TOK + pos] : -1;
        sW[t]    = ok ? g_wlist[e * B_TOK + pos] : 0.f;
    }
    if (t < NT) sBias[t] = b2[(size_t)e * ODIM + n0 + t];
    __syncthreads();

    const int ar = t >> 2;
    const int q = t & 3;
    const int ent = sEnt[ar];
    const int row = (ent < 0 ? 0 : ent);
    const __half* aS = g_h16 + (size_t)row * HDIM + q * 16;
    uint32_t aswo[2];
#pragma unroll
    for (int i = 0; i < 2; i++) aswo[i] = SW((uint32_t)ar * 128 + q * 32 + 16 * i);
    const int br1 = t >> 3, bo1 = (t & 7) * 16;
    const __half* bW = g_W2t + ((size_t)e * ODIM + n0) * HDIM;
    const uint32_t bswo1 = SW((uint32_t)br1 * 128 + bo1);
    const int br2 = 96 + (t >> 3);
    const uint32_t bswo2 = SW((uint32_t)br2 * 128 + bo1);

    auto issue = [&](int kt) {
        uint32_t dst = sb + OFF_T + (uint32_t)(kt & 3) * STAGE;
        const size_t ko = (size_t)kt * KC;
#pragma unroll
        for (int i = 0; i < 2; i++)
            CP16(dst + aswo[i], aS + ko + i * 8);
        CP16(dst + B_OFF + bswo1, bW + (size_t)br1 * HDIM + ko + bo1 / 2);
        if (t < 256)
            CP16(dst + B_OFF + bswo2, bW + (size_t)br2 * HDIM + ko + bo1 / 2);
        CP_COMMIT();
    };

    const int wm = (wid >> 2) * 32, wn = (wid & 3) * 32;
    const int rA = wm + (lane & 7) + ((lane >> 3) & 1) * 8, aSel = (lane >> 4) & 1;
    const int rB = wn + (lane & 7) + ((lane >> 4) & 1) * 8, bSel = (lane >> 3) & 1;

    float acc[2][4][4];
#pragma unroll
    for (int a = 0; a < 2; a++)
#pragma unroll
        for (int bq = 0; bq < 4; bq++)
#pragma unroll
            for (int c = 0; c < 4; c++) acc[a][bq][c] = 0.f;

    const int NS = HDIM / KC;  // 32
    issue(0); issue(1); issue(2);
    for (int kt = 0; kt < NS; kt++) {
        if (kt <= NS - 3)      { CP_WAIT2(); }
        else if (kt == NS - 2) { CP_WAIT1(); }
        else                   { CP_WAIT0(); }
        __syncthreads();
        if (kt + 3 < NS) issue(kt + 3);
        mma_stage(sb, kt & 3, rA, aSel, rB, bSel, acc);
    }

    // epilogue: atomicAdd w*(acc+bias) into out[token]  (2 adds/element,
    // commutative fp add -> bitwise deterministic)
    const int crow = lane >> 2, ccol = (lane & 3) * 2;
#pragma unroll
    for (int mi = 0; mi < 2; mi++)
#pragma unroll
        for (int h = 0; h < 2; h++) {
            const int ml = wm + mi * 16 + crow + h * 8;
            const int entm = sEnt[ml];
            if (entm < 0) continue;
            const float wt = sW[ml];
            float* op = out + (size_t)(entm >> 1) * ODIM + n0;
#pragma unroll
            for (int ni = 0; ni < 4; ni++) {
                const int tn = wn + ni * 8 + ccol;
                atomicAdd(op + tn,     (acc[mi][ni][h * 2 + 0] + sBias[tn]) * wt);
                atomicAdd(op + tn + 1, (acc[mi][ni][h * 2 + 1] + sBias[tn + 1]) * wt);
            }
        }
}

// ============================ launch =========================================
// Order keeps gemm1 at launch index 3 (ncu profiles index 3).
extern "C" void kernel_launch(void* const* d_in, const int* in_sizes, int n_in,
                              void* d_out, int out_size) {
    const float* x  = (const float*)d_in[0];
    const float* Wg = (const float*)d_in[1];
    const float* bg = (const float*)d_in[2];
    const float* W1 = (const float*)d_in[3];
    const float* b1 = (const float*)d_in[4];
    const float* W2 = (const float*)d_in[5];
    const float* b2 = (const float*)d_in[6];
    float* out = (float*)d_out;

    static int smem_set = 0;
    if (!smem_set) {
        cudaFuncSetAttribute(gemm1_mma, cudaFuncAttributeMaxDynamicSharedMemorySize, SMEM_BYTES);
        cudaFuncSetAttribute(gemm2_mma, cudaFuncAttributeMaxDynamicSharedMemorySize, SMEM_BYTES);
        smem_set = 1;
    }

    const int YB = (B_TOK + MT - 1) / MT;   // 43

    convW1_kernel<<<dim3(HDIM / 32, DDIM / 32, NEXP), dim3(32, 8)>>>(W1);
    zero_counts_kernel<<<1, 32>>>();
    gate_kernel<<<B_TOK / 8, 256>>>(x, Wg, bg, out);

    gemm1_mma<<<dim3(HDIM / NT, YB, NEXP), NTHR, SMEM_BYTES>>>(b1);

    convW2_kernel<<<dim3(ODIM / 32, HDIM / 32, NEXP), dim3(32, 8)>>>(W2);
    gemm2_mma<<<dim3(ODIM / NT, YB, NEXP), NTHR, SMEM_BYTES>>>(b2, out);
}